// round 3
// baseline (speedup 1.0000x reference)
#include <cuda_runtime.h>
#include <stdint.h>

#define HH 256
#define WW 256
#define NPIX (HH*WW)

// spiral rank of displacement s = (dj+3)*7 + (di+3), center-out spiral
__constant__ int c_spiral[49] = {
    42,43,44,45,46,47,48,
    41,20,21,22,23,24,25,
    40,19, 6, 7, 8, 9,26,
    39,18, 5, 0, 1,10,27,
    38,17, 4, 3, 2,11,28,
    37,16,15,14,13,12,29,
    36,35,34,33,32,31,30
};

__device__ __forceinline__ float imload(const float* __restrict__ img, int y, int x) {
    y = min(max(y, 0), HH - 1);
    x = min(max(x, 0), WW - 1);
    return __ldg(&img[y * WW + x]);
}

__device__ __forceinline__ unsigned char quant(float v) {
    float r = rintf(v * 255.0f);          // round half-to-even, matches jnp.round
    r = fminf(fmaxf(r, 0.0f), 255.0f);
    return (unsigned char)r;
}

__device__ __forceinline__ void mnmx(float& a, float& b) {
    float t = fminf(a, b);
    b = fmaxf(a, b);
    a = t;
}
__device__ __forceinline__ float median9(float p0, float p1, float p2,
                                         float p3, float p4, float p5,
                                         float p6, float p7, float p8) {
    mnmx(p1, p2); mnmx(p4, p5); mnmx(p7, p8);
    mnmx(p0, p1); mnmx(p3, p4); mnmx(p6, p7);
    mnmx(p1, p2); mnmx(p4, p5); mnmx(p7, p8);
    mnmx(p0, p3); mnmx(p5, p8); mnmx(p4, p7);
    mnmx(p3, p6); mnmx(p1, p4); mnmx(p2, p5);
    mnmx(p4, p7); mnmx(p4, p2); mnmx(p6, p4);
    mnmx(p4, p2);
    return p4;
}

// =====================================================================
// Single fused kernel: binomial -> quantize -> gradient -> block match
// -> subpixel -> median -> bilateral.  16x16 output tile per block;
// flow computed on a 22x22 region (halo 3) with clamped coordinates
// (== replicate padding for the median stage).
// =====================================================================
__global__ __launch_bounds__(512, 2) void flow_kernel(const float* __restrict__ f,
                                                      const float* __restrict__ g,
                                                      float* __restrict__ out) {
    // f pipeline
    __shared__ float rawf[34][34];            // origin (by-9, bx-9)
    __shared__ float vertf[32][34];           // rows (by-8), cols (bx-9)
    __shared__ float sfb[32][32];             // origin (by-8, bx-8)
    __shared__ unsigned char sfq[32][40];     // origin (by-8, bx-8); cols 32..39 zero
    __shared__ unsigned int sfqs[4][32][10];  // byte-shifted copies of sfq rows
    // g pipeline
    __shared__ float rawg[28][28];            // origin (by-6, bx-6)
    __shared__ float vertg[26][28];           // rows (by-5), cols (bx-6)
    __shared__ unsigned char sgq[26][28];     // origin (by-5, bx-5); cols 26..27 zero
    // gradients of fb on (by-5, bx-5) .. 26x26, zero outside image
    __shared__ float sdx[26][26];
    __shared__ float sdy[26][26];
    // flow on F = (by-3, bx-3) .. 22x22 (clamped pixels)
    __shared__ float sflow0[22][22];
    __shared__ float sflow1[22][22];
    // median + guide on M = (by-2, bx-2) .. 20x20, zero outside image
    __shared__ float smed0[20][20];
    __shared__ float smed1[20][20];
    __shared__ float sguide[20][20];

    const int bx = blockIdx.x * 16, by = blockIdx.y * 16;
    const int tid = threadIdx.x;

    // ---- phase 1: raw loads (replicate clamp) ----
    for (int i = tid; i < 34 * 34; i += 512) {
        int r = i / 34, c = i % 34;
        rawf[r][c] = imload(f, by - 9 + r, bx - 9 + c);
    }
    for (int i = tid; i < 28 * 28; i += 512) {
        int r = i / 28, c = i % 28;
        rawg[r][c] = imload(g, by - 6 + r, bx - 6 + c);
    }
    __syncthreads();

    // ---- phase 2: vertical binomial ----
    for (int i = tid; i < 32 * 34; i += 512) {
        int r = i / 34, c = i % 34;
        vertf[r][c] = (rawf[r][c] + 2.0f * rawf[r + 1][c] + rawf[r + 2][c]) * 0.25f;
    }
    for (int i = tid; i < 26 * 28; i += 512) {
        int r = i / 28, c = i % 28;
        vertg[r][c] = (rawg[r][c] + 2.0f * rawg[r + 1][c] + rawg[r + 2][c]) * 0.25f;
    }
    __syncthreads();

    // ---- phase 3: horizontal binomial + quantize ----
    for (int i = tid; i < 32 * 32; i += 512) {
        int r = i / 32, c = i % 32;
        float fb = (vertf[r][c] + 2.0f * vertf[r][c + 1] + vertf[r][c + 2]) * 0.25f;
        sfb[r][c] = fb;
        int y = by - 8 + r, x = bx - 8 + c;
        bool in = (y >= 0 && y < HH && x >= 0 && x < WW);
        sfq[r][c] = in ? quant(fb) : (unsigned char)0;
    }
    for (int i = tid; i < 32 * 8; i += 512) {           // zero pad cols 32..39
        int r = i / 8, c = 32 + i % 8;
        sfq[r][c] = 0;
    }
    for (int i = tid; i < 26 * 28; i += 512) {
        int r = i / 28, c = i % 28;
        unsigned char v = 0;
        if (c < 26) {
            float gb = (vertg[r][c] + 2.0f * vertg[r][c + 1] + vertg[r][c + 2]) * 0.25f;
            int y = by - 5 + r, x = bx - 5 + c;
            bool in = (y >= 0 && y < HH && x >= 0 && x < WW);
            v = in ? quant(gb) : (unsigned char)0;
        }
        sgq[r][c] = v;
    }
    __syncthreads();

    // ---- phase 4: shifted fq copies + gradient ----
    for (int i = tid; i < 4 * 32 * 8; i += 512) {
        int k = i >> 8;                  // 0..3
        int rem = i & 255;               // 32*8
        int r = rem >> 3, w = rem & 7;   // word 0..7
        const unsigned int* W = (const unsigned int*)sfq[r];
        sfqs[k][r][w] = __byte_perm(W[w], W[w + 1], 0x3210u + (unsigned)k * 0x1111u);
    }
    for (int i = tid; i < 26 * 26; i += 512) {
        int r = i / 26, c = i % 26;
        int y = by - 5 + r, x = bx - 5 + c;
        bool in = (y >= 0 && y < HH && x >= 0 && x < WW);
        float dyv = 0.0f, dxv = 0.0f;
        if (in) {
            int yn = min(y + 1, HH - 1) - (by - 8);
            int yp = max(y - 1, 0) - (by - 8);
            int xn = min(x + 1, WW - 1) - (bx - 8);
            int xp = max(x - 1, 0) - (bx - 8);
            dyv = (sfb[yn][c + 3] - sfb[yp][c + 3]) * 0.5f;
            dxv = (sfb[r + 3][xn] - sfb[r + 3][xp]) * 0.5f;
        }
        sdy[r][c] = dyv;
        sdx[r][c] = dxv;
    }
    __syncthreads();

    // ---- phase 5: block match + subpixel on the 22x22 flow region ----
    if (tid < 484) {
        int rF = tid / 22, cF = tid % 22;
        int py = min(max(by - 3 + rF, 0), HH - 1);    // clamped pixel (replicate)
        int px = min(max(bx - 3 + cF, 0), WW - 1);
        int ly = py - by;                 // [-3, 18]
        int lx = px - (bx - 8);           // [5, 26]
        int lgy = py - (by - 5);          // [2, 23]
        int lgx = px - (bx - 5);

        // g template: 5 rows, 4+1 bytes
        unsigned int glo[5], ghib[5];
        {
            int o2 = lgx - 2;
            int k2 = o2 & 3, w2 = o2 >> 2;
            unsigned int sel = 0x3210u + (unsigned)k2 * 0x1111u;
            #pragma unroll
            for (int ky = 0; ky < 5; ky++) {
                const unsigned int* row = (const unsigned int*)sgq[lgy - 2 + ky];
                unsigned int a = row[w2], b2 = row[w2 + 1];
                glo[ky] = __byte_perm(a, b2, sel);
                ghib[ky] = (b2 >> (8 * k2)) & 0xFFu;
            }
        }

        int best = 0x7fffffff;
        int row0 = ly + 3;
        #pragma unroll 1
        for (int dip = 0; dip < 7; dip++) {
            int o = lx + dip - 5;
            int k = o & 3, wi = o >> 2;
            const unsigned int* basep = &sfqs[k][0][wi];
            unsigned int flo[11], fhi[11];
            #pragma unroll
            for (int r = 0; r < 11; r++) {
                const unsigned int* rp = basep + (row0 + r) * 10;
                flo[r] = rp[0];
                fhi[r] = rp[1] & 0xFFu;
            }
            #pragma unroll
            for (int djp = 0; djp < 7; djp++) {
                unsigned int sad = 0;
                #pragma unroll
                for (int ky = 0; ky < 5; ky++) {
                    sad = __dp4a(__vabsdiffu4(flo[djp + ky], glo[ky]), 0x01010101u, sad);
                    sad = __usad(fhi[djp + ky], ghib[ky], sad);
                }
                int s = djp * 7 + dip;
                int packed = (((int)sad * 64 + c_spiral[s]) << 6) | s;
                best = min(best, packed);
            }
        }
        int bestS = best & 63;
        int bjp = bestS / 7, bip = bestS % 7;

        // Lucas-Kanade subpixel on the 5x5 border ring
        float a = 0.f, b = 0.f, d = 0.f, p = 0.f, q = 0.f;
        #pragma unroll
        for (int ky = 0; ky < 5; ky++) {
            #pragma unroll
            for (int kx = 0; kx < 5; kx++) {
                if (ky == 0 || ky == 4 || kx == 0 || kx == 4) {
                    float dx = sdx[lgy - 2 + ky][lgx - 2 + kx];
                    float dy = sdy[lgy - 2 + ky][lgx - 2 + kx];
                    float fv = (float)sfq[row0 + bjp + ky][lx + bip + kx - 5] * (1.0f / 255.0f);
                    unsigned int gb = (kx < 4) ? ((glo[ky] >> (8 * kx)) & 0xFFu) : ghib[ky];
                    float gv = (float)gb * (1.0f / 255.0f);
                    float z = gv - fv;
                    a += dx * dx;
                    b += dx * dy;
                    d += dy * dy;
                    p += z * dx;
                    q += z * dy;
                }
            }
        }
        // avoid FMA contraction: thresholds must match the reference rounding
        float det = __fsub_rn(__fmul_rn(a, d), __fmul_rn(b, b));
        float u   = __fsub_rn(__fmul_rn(d, p), __fmul_rn(b, q));
        float v   = __fsub_rn(__fmul_rn(a, q), __fmul_rn(b, p));
        bool bad = (det <= 1e-7f);
        float dd = bad ? 1.0f : det;
        float sv = v / dd;   // y component
        float su = u / dd;   // x component
        if (bad || fabsf(sv) >= 1.0f) sv = 0.0f;
        if (bad || fabsf(su) >= 1.0f) su = 0.0f;

        sflow0[rF][cF] = (float)(3 - bjp) + sv;   // -dj
        sflow1[rF][cF] = (float)(3 - bip) + su;   // -di
    }
    __syncthreads();

    // ---- phase 6: 3x3 median (replicate) + guide staging on 20x20 ----
    for (int i = tid; i < 20 * 20; i += 512) {
        int rM = i / 20, cM = i % 20;
        int y = by - 2 + rM, x = bx - 2 + cM;
        bool in = (y >= 0 && y < HH && x >= 0 && x < WW);
        float m0 = 0.0f, m1 = 0.0f, gd = 0.0f;
        if (in) {
            int ym = max(y - 1, 0) - (by - 3);
            int y0 = y - (by - 3);
            int yp = min(y + 1, HH - 1) - (by - 3);
            int xm = max(x - 1, 0) - (bx - 3);
            int x0 = x - (bx - 3);
            int xp = min(x + 1, WW - 1) - (bx - 3);
            m0 = median9(sflow0[ym][xm], sflow0[ym][x0], sflow0[ym][xp],
                         sflow0[y0][xm], sflow0[y0][x0], sflow0[y0][xp],
                         sflow0[yp][xm], sflow0[yp][x0], sflow0[yp][xp]);
            m1 = median9(sflow1[ym][xm], sflow1[ym][x0], sflow1[ym][xp],
                         sflow1[y0][xm], sflow1[y0][x0], sflow1[y0][xp],
                         sflow1[yp][xm], sflow1[yp][x0], sflow1[yp][xp]);
            gd = sfb[rM + 6][cM + 6];
        }
        smed0[rM][cM] = m0;
        smed1[rM][cM] = m1;
        sguide[rM][cM] = gd;
    }
    __syncthreads();

    // ---- phase 7: bilateral smoothing (zero pad) + output ----
    if (tid < 256) {
        int ty = tid >> 4, tx = tid & 15;
        const float KVAL = -1.0f / 4.5f;   // -1/(2*1.5^2)
        const float SII  = 200.0f;         //  1/(2*0.05^2)
        float c = sguide[ty + 2][tx + 2];
        float wsum = 0.f, s0 = 0.f, s1 = 0.f;
        #pragma unroll
        for (int dy = 0; dy < 5; dy++) {
            #pragma unroll
            for (int dx = 0; dx < 5; dx++) {
                float tn = sguide[ty + dy][tx + dx];   // zero outside image
                float df = c - tn;
                float co = 1.0f - fabsf(KVAL - df * df * SII);
                co = fminf(fmaxf(co, 0.0f), 1.0f);
                wsum += co;                            // OOB still weighs denom
                s0 += smed0[ty + dy][tx + dx] * co;
                s1 += smed1[ty + dy][tx + dx] * co;
            }
        }
        int y = by + ty, x = bx + tx;
        out[y * WW + x]        = s0 / wsum;
        out[NPIX + y * WW + x] = s1 / wsum;
    }
}

// ---------------- launch ----------------
extern "C" void kernel_launch(void* const* d_in, const int* in_sizes, int n_in,
                              void* d_out, int out_size) {
    const float* f = (const float*)d_in[0];
    const float* g = (const float*)d_in[1];
    float* out = (float*)d_out;

    dim3 grd(WW / 16, HH / 16);
    flow_kernel<<<grd, 512>>>(f, g, out);
}

// round 4
// speedup vs baseline: 1.2879x; 1.2879x over previous
#include <cuda_runtime.h>
#include <stdint.h>

#define HH 256
#define WW 256
#define NPIX (HH*WW)

// ---------------- scratch (device globals; no allocations allowed) -------------
__device__ float g_fb[NPIX];        // binomial-filtered f (guide for bilateral)
__device__ float g_flow1[2*NPIX];   // vector + subpixel (before median)

// spiral rank of displacement s = (dj+3)*7 + (di+3), center-out spiral
__constant__ int c_spiral[49] = {
    42,43,44,45,46,47,48,
    41,20,21,22,23,24,25,
    40,19, 6, 7, 8, 9,26,
    39,18, 5, 0, 1,10,27,
    38,17, 4, 3, 2,11,28,
    37,16,15,14,13,12,29,
    36,35,34,33,32,31,30
};

__device__ __forceinline__ float imload(const float* __restrict__ img, int y, int x) {
    y = min(max(y, 0), HH - 1);
    x = min(max(x, 0), WW - 1);
    return __ldg(&img[y * WW + x]);
}

__device__ __forceinline__ unsigned char quant(float v) {
    float r = rintf(v * 255.0f);          // round half-to-even, matches jnp.round
    r = fminf(fmaxf(r, 0.0f), 255.0f);
    return (unsigned char)r;
}

// =====================================================================
// Kernel A: binomial + quantize + gradient + block match + subpixel.
// 16x16 tile, 512 threads = 2 threads/pixel (z splits the 7 dip columns).
// =====================================================================
__global__ __launch_bounds__(512, 2) void matchA_kernel(const float* __restrict__ f,
                                                        const float* __restrict__ g) {
    // f pipeline: raw 28x28 (origin by-6,bx-6) -> vert 26x28 -> fb 26x26 (by-5,bx-5)
    __shared__ float rawf[28][28];
    __shared__ float vertf[26][28];
    __shared__ float sfb[26][26];
    __shared__ __align__(16) unsigned char sfq[26][32];   // cols 26..31 zero
    __shared__ uint32_t sfqs[26][4][13];                    // shifted copies, words 0..6 used
    // g pipeline: raw 22x22 (by-3,bx-3) -> vert 20x22 -> gq 20x24 (by-2,bx-2)
    __shared__ float rawg[22][22];
    __shared__ float vertg[20][22];
    __shared__ __align__(16) unsigned char sgq[20][24];    // cols 0..19 data
    // gradient of fb on (by-2,bx-2) 20x20
    __shared__ float sdx[20][20];
    __shared__ float sdy[20][20];

    const int bx = blockIdx.x * 16, by = blockIdx.y * 16;
    const int tid = threadIdx.x;
    const int p  = tid >> 1;          // pixel 0..255
    const int z  = tid & 1;           // dip-group
    const int ty = p >> 4, tx = p & 15;

    // ---- phase 1: raw loads (replicate clamp) ----
    for (int i = tid; i < 28 * 28; i += 512) {
        int r = i / 28, c = i % 28;
        rawf[r][c] = imload(f, by - 6 + r, bx - 6 + c);
    }
    for (int i = tid; i < 22 * 22; i += 512) {
        int r = i / 22, c = i % 22;
        rawg[r][c] = imload(g, by - 3 + r, bx - 3 + c);
    }
    __syncthreads();

    // ---- phase 2: vertical binomial ----
    for (int i = tid; i < 26 * 28; i += 512) {
        int r = i / 28, c = i % 28;
        vertf[r][c] = (rawf[r][c] + 2.0f * rawf[r + 1][c] + rawf[r + 2][c]) * 0.25f;
    }
    for (int i = tid; i < 20 * 22; i += 512) {
        int r = i / 22, c = i % 22;
        vertg[r][c] = (rawg[r][c] + 2.0f * rawg[r + 1][c] + rawg[r + 2][c]) * 0.25f;
    }
    __syncthreads();

    // ---- phase 3: horizontal binomial + quantize ----
    for (int i = tid; i < 26 * 32; i += 512) {
        int r = i / 32, c = i % 32;
        unsigned char v = 0;
        if (c < 26) {
            float fb = (vertf[r][c] + 2.0f * vertf[r][c + 1] + vertf[r][c + 2]) * 0.25f;
            sfb[r][c] = fb;
            int y = by - 5 + r, x = bx - 5 + c;
            bool in = (y >= 0 && y < HH && x >= 0 && x < WW);
            v = in ? quant(fb) : (unsigned char)0;
        }
        sfq[r][c] = v;
    }
    for (int i = tid; i < 20 * 20; i += 512) {
        int r = i / 20, c = i % 20;
        float gb = (vertg[r][c] + 2.0f * vertg[r][c + 1] + vertg[r][c + 2]) * 0.25f;
        int y = by - 2 + r, x = bx - 2 + c;
        bool in = (y >= 0 && y < HH && x >= 0 && x < WW);
        sgq[r][c] = in ? quant(gb) : (unsigned char)0;
    }
    __syncthreads();

    // ---- phase 4: shifted fq copies + gradient of fb ----
    for (int i = tid; i < 26 * 28; i += 512) {
        int r = i / 28, rem = i % 28;
        int k = rem / 7, w = rem % 7;
        const uint32_t* W = (const uint32_t*)sfq[r];
        sfqs[r][k][w] = __byte_perm(W[w], W[w + 1], 0x3210u + (unsigned)k * 0x1111u);
    }
    for (int i = tid; i < 20 * 20; i += 512) {
        int r = i / 20, c = i % 20;
        int y = by - 2 + r, x = bx - 2 + c;
        bool in = (y >= 0 && y < HH && x >= 0 && x < WW);
        float dyv = 0.0f, dxv = 0.0f;
        if (in) {
            int yn = min(y + 1, HH - 1) - (by - 5);
            int yp = max(y - 1, 0) - (by - 5);
            int xn = min(x + 1, WW - 1) - (bx - 5);
            int xp = max(x - 1, 0) - (bx - 5);
            dyv = (sfb[yn][c + 3] - sfb[yp][c + 3]) * 0.5f;
            dxv = (sfb[r + 3][xn] - sfb[r + 3][xp]) * 0.5f;
        }
        sdy[r][c] = dyv;
        sdx[r][c] = dxv;
    }
    __syncthreads();

    // ---- g template: 5 rows (4 bytes + 1 byte), origin col tx in sgq ----
    unsigned int glo[5], ghib[5];
    {
        int k2 = tx & 3, w2 = tx >> 2;
        unsigned int sel = 0x3210u + (unsigned)k2 * 0x1111u;
        #pragma unroll
        for (int ky = 0; ky < 5; ky++) {
            const uint32_t* row = (const uint32_t*)sgq[ty + ky];
            uint32_t a = row[w2], b2 = row[w2 + 1];
            glo[ky]  = __byte_perm(a, b2, sel);
            ghib[ky] = (b2 >> (8 * k2)) & 0xFFu;
        }
    }

    // ---- SAD over assigned dips, conflict-free shifted-copy loads ----
    int best = 0x7fffffff;
    const int dip0 = z ? 4 : 0;
    const int dip1 = z ? 7 : 4;
    for (int dip = dip0; dip < dip1; ++dip) {
        int s = tx + dip;                 // byte window start in sfq row
        int k = s & 3, wi = s >> 2;
        const uint32_t* bp = &sfqs[ty][k][wi];
        uint32_t flo[11], fhi[11];
        #pragma unroll
        for (int r = 0; r < 11; r++) {
            const uint32_t* rp = bp + r * 52;   // next fq row = 4*13 words
            flo[r] = rp[0];
            fhi[r] = rp[1] & 0xFFu;
        }
        #pragma unroll
        for (int djp = 0; djp < 7; djp++) {
            unsigned int sad = 0;
            #pragma unroll
            for (int ky = 0; ky < 5; ky++) {
                sad = __dp4a(__vabsdiffu4(flo[djp + ky], glo[ky]), 0x01010101u, sad);
                sad = __usad(fhi[djp + ky], ghib[ky], sad);
            }
            int sidx = djp * 7 + dip;
            int packed = (((int)sad * 64 + c_spiral[sidx]) << 6) | sidx;
            best = min(best, packed);
        }
    }
    // merge the two dip-groups of this pixel (lanes 2p / 2p+1)
    best = min(best, __shfl_xor_sync(0xffffffffu, best, 1));

    int bestS = best & 63;
    int bjp = bestS / 7, bip = bestS % 7;

    // ---- Lucas-Kanade subpixel on the 5x5 border ring (both lanes compute) ----
    float a = 0.f, b = 0.f, d = 0.f, pp = 0.f, q = 0.f;
    #pragma unroll
    for (int ky = 0; ky < 5; ky++) {
        #pragma unroll
        for (int kx = 0; kx < 5; kx++) {
            if (ky == 0 || ky == 4 || kx == 0 || kx == 4) {
                float dx = sdx[ty + ky][tx + kx];
                float dy = sdy[ty + ky][tx + kx];
                float fv = (float)sfq[ty + bjp + ky][tx + bip + kx] * (1.0f / 255.0f);
                unsigned int gb = (kx < 4) ? ((glo[ky] >> (8 * kx)) & 0xFFu) : ghib[ky];
                float gv = (float)gb * (1.0f / 255.0f);
                float zd = gv - fv;
                a  += dx * dx;
                b  += dx * dy;
                d  += dy * dy;
                pp += zd * dx;
                q  += zd * dy;
            }
        }
    }
    // avoid FMA contraction: thresholds must match the reference rounding
    float det = __fsub_rn(__fmul_rn(a, d), __fmul_rn(b, b));
    float u   = __fsub_rn(__fmul_rn(d, pp), __fmul_rn(b, q));
    float v   = __fsub_rn(__fmul_rn(a, q), __fmul_rn(b, pp));
    bool bad = (det <= 1e-7f);
    float dd = bad ? 1.0f : det;
    float sv = v / dd;   // y component
    float su = u / dd;   // x component
    if (bad || fabsf(sv) >= 1.0f) sv = 0.0f;
    if (bad || fabsf(su) >= 1.0f) su = 0.0f;

    if (z == 0) {
        int y = by + ty, x = bx + tx;
        g_fb[y * WW + x]           = sfb[ty + 5][tx + 5];
        g_flow1[y * WW + x]        = (float)(3 - bjp) + sv;   // -dj
        g_flow1[NPIX + y * WW + x] = (float)(3 - bip) + su;   // -di
    }
}

// =====================================================================
// Kernel B: 3x3 median (replicate) + bilateral smoothing (zero pad).
// 16x16 tile, 512 threads = 2 threads/pixel (z = flow channel).
// =====================================================================
__device__ __forceinline__ void mnmx(float& a, float& b) {
    float t = fminf(a, b);
    b = fmaxf(a, b);
    a = t;
}
__device__ __forceinline__ float median9(float p0, float p1, float p2,
                                         float p3, float p4, float p5,
                                         float p6, float p7, float p8) {
    mnmx(p1, p2); mnmx(p4, p5); mnmx(p7, p8);
    mnmx(p0, p1); mnmx(p3, p4); mnmx(p6, p7);
    mnmx(p1, p2); mnmx(p4, p5); mnmx(p7, p8);
    mnmx(p0, p3); mnmx(p5, p8); mnmx(p4, p7);
    mnmx(p3, p6); mnmx(p1, p4); mnmx(p2, p5);
    mnmx(p4, p7); mnmx(p4, p2); mnmx(p6, p4);
    mnmx(p4, p2);
    return p4;
}

__global__ __launch_bounds__(512, 2) void smoothB_kernel(float* __restrict__ out) {
    __shared__ float sflow[2][22][22];   // flow halo 3, replicate clamp
    __shared__ float smed[2][20][20];    // median flow, halo 2, zero outside image
    __shared__ float sguide[20][20];     // fb guide, halo 2, zero outside image

    const int bx = blockIdx.x * 16, by = blockIdx.y * 16;
    const int tid = threadIdx.x;

    for (int i = tid; i < 2 * 484; i += 512) {
        int ch = i >= 484;
        int rem = i - ch * 484;
        int r = rem / 22, c = rem % 22;
        int y = min(max(by - 3 + r, 0), HH - 1);
        int x = min(max(bx - 3 + c, 0), WW - 1);
        sflow[ch][r][c] = g_flow1[ch * NPIX + y * WW + x];
    }
    __syncthreads();

    for (int i = tid; i < 2 * 400; i += 512) {
        int ch = i >= 400;
        int rem = i - ch * 400;
        int r = rem / 20, c = rem % 20;
        int y = by - 2 + r, x = bx - 2 + c;
        bool in = (y >= 0 && y < HH && x >= 0 && x < WW);
        float m = 0.0f;
        if (in) {
            int ym = max(y - 1, 0) - (by - 3);
            int y0 = y - (by - 3);
            int yp = min(y + 1, HH - 1) - (by - 3);
            int xm = max(x - 1, 0) - (bx - 3);
            int x0 = x - (bx - 3);
            int xp = min(x + 1, WW - 1) - (bx - 3);
            const float (*fl)[22] = sflow[ch];
            m = median9(fl[ym][xm], fl[ym][x0], fl[ym][xp],
                        fl[y0][xm], fl[y0][x0], fl[y0][xp],
                        fl[yp][xm], fl[yp][x0], fl[yp][xp]);
        }
        smed[ch][r][c] = m;
        if (ch == 0) sguide[r][c] = in ? g_fb[y * WW + x] : 0.0f;
    }
    __syncthreads();

    {
        int p = tid >> 1, ch = tid & 1;
        int ty = p >> 4, tx = p & 15;
        const float KVAL = -1.0f / 4.5f;   // -1/(2*1.5^2)
        const float SII  = 200.0f;         //  1/(2*0.05^2)
        float c = sguide[ty + 2][tx + 2];
        float wsum = 0.f, s = 0.f;
        const float (*md)[20] = smed[ch];
        #pragma unroll
        for (int dy = 0; dy < 5; dy++) {
            #pragma unroll
            for (int dx = 0; dx < 5; dx++) {
                float tn = sguide[ty + dy][tx + dx];   // zero outside image
                float df = c - tn;
                float co = 1.0f - fabsf(KVAL - df * df * SII);
                co = fminf(fmaxf(co, 0.0f), 1.0f);
                wsum += co;                            // OOB still weighs denom
                s += md[ty + dy][tx + dx] * co;
            }
        }
        int y = by + ty, x = bx + tx;
        out[ch * NPIX + y * WW + x] = s / wsum;
    }
}

// ---------------- launch ----------------
extern "C" void kernel_launch(void* const* d_in, const int* in_sizes, int n_in,
                              void* d_out, int out_size) {
    const float* f = (const float*)d_in[0];
    const float* g = (const float*)d_in[1];
    float* out = (float*)d_out;

    dim3 grd(WW / 16, HH / 16);
    matchA_kernel<<<grd, 512>>>(f, g);
    smoothB_kernel<<<grd, 512>>>(out);
}